// round 14
// baseline (speedup 1.0000x reference)
#include <cuda_runtime.h>
#include <cuda_fp16.h>

#define HWSZ 262144           // 512*512
#define NB 8
#define FDIM 257              // live quadrant: x0,y0 in [255,511]
#define FOFF (255 * FDIM + 255)
#define FSZ (FDIM * FDIM)

// 5 scalar sample fields f_k = dot(w2_k, img), quad-packed, quadrant only.
__device__ uint2 g_f[5 * NB * FSZ];

// ---------------------------------------------------------------------------
__device__ __forceinline__ unsigned long long pk2(float lo, float hi) {
    unsigned long long r;
    asm("mov.b64 %0, {%1, %2};" : "=l"(r) : "f"(lo), "f"(hi));
    return r;
}
__device__ __forceinline__ void upk2(float& lo, float& hi, unsigned long long v) {
    asm("mov.b64 {%0, %1}, %2;" : "=f"(lo), "=f"(hi) : "l"(v));
}
__device__ __forceinline__ unsigned long long fma2(unsigned long long a,
                                                   unsigned long long b,
                                                   unsigned long long c) {
    unsigned long long d;
    asm("fma.rn.f32x2 %0, %1, %2, %3;" : "=l"(d) : "l"(a), "l"(b), "l"(c));
    return d;
}

// ---------------------------------------------------------------------------
// Kernel 1: build the quadrant fields. grid (9,9,8), block (32,8).
// ---------------------------------------------------------------------------
__global__ __launch_bounds__(256) void k_prep(const float* __restrict__ x,
                                              const float* __restrict__ w2) {
    __shared__ float4 tile[33][33];
    __shared__ float4 s_w2[5];
    int b  = blockIdx.z;
    int h0 = 255 + (blockIdx.y << 5);
    int w0 = 255 + (blockIdx.x << 5);
    int tx = threadIdx.x, ty = threadIdx.y;
    int t = (ty << 5) + tx;
    if (t < 5) s_w2[t] = make_float4(w2[3 * t], w2[3 * t + 1], w2[3 * t + 2], 0.f);

    const float* xb = x + (size_t)b * 3 * HWSZ;
#pragma unroll
    for (int r = 0; r < 5; r++) {
        int rr = ty + (r << 3);
        if (rr < 33) {
            int hh = h0 + rr;
#pragma unroll
            for (int jj = 0; jj < 2; jj++) {
                int j = tx + (jj << 5);
                if (j < 33) {
                    int ww = w0 + j;
                    float4 v = make_float4(0.f, 0.f, 0.f, 0.f);
                    if (hh < 512 && ww < 512) {
                        int hw = (hh << 9) + ww;
                        v = make_float4(xb[hw], xb[HWSZ + hw], xb[2 * HWSZ + hw], 0.f);
                    }
                    tile[rr][j] = v;
                }
            }
        }
    }
    __syncthreads();

    int fy = h0 + tx - 255;
    if (fy >= FDIM) return;
#pragma unroll
    for (int r = 0; r < 4; r++) {
        int cc = ty + (r << 3);
        int fx = w0 + cc - 255;
        if (fx >= FDIM) continue;
        float4 v00 = tile[tx][cc];
        float4 v01 = tile[tx + 1][cc];
        float4 v10 = tile[tx][cc + 1];
        float4 v11 = tile[tx + 1][cc + 1];
        int base = fx * FDIM + fy;
#pragma unroll
        for (int k = 0; k < 5; k++) {
            float4 wv = s_w2[k];
            float f00 = v00.x * wv.x + v00.y * wv.y + v00.z * wv.z;
            float f01 = v01.x * wv.x + v01.y * wv.y + v01.z * wv.z;
            float f10 = v10.x * wv.x + v10.y * wv.y + v10.z * wv.z;
            float f11 = v11.x * wv.x + v11.y * wv.y + v11.z * wv.z;
            __half2 pa = __floats2half2_rn(f00, f01);
            __half2 pb = __floats2half2_rn(f10, f11);
            uint2 q;
            q.x = *reinterpret_cast<unsigned*>(&pa);
            q.y = *reinterpret_cast<unsigned*>(&pb);
            g_f[(k * NB + b) * FSZ + base] = q;
        }
    }
}

// ---------------------------------------------------------------------------
// Bilinear sample of a quadrant field (branchy early-out, R8-proven):
// ONE scattered 8B load + 6 flops.
// ---------------------------------------------------------------------------
__device__ __forceinline__ void samp(const uint2* __restrict__ fld,
                                     float gx, float gy, float& acc) {
    float ix = fmaf(gx, 256.f, 255.5f);
    float iy = fmaf(gy, 256.f, 255.5f);
    if (ix >= 512.f || iy >= 512.f) return;
    int x0 = (int)ix, y0 = (int)iy;
    float wx1 = ix - (float)x0, wy1 = iy - (float)y0;
    uint2 q = __ldg(fld + (x0 * FDIM + y0 - FOFF));
    float2 fa = __half22float2(*reinterpret_cast<__half2*>(&q.x));
    float2 fb = __half22float2(*reinterpret_cast<__half2*>(&q.y));
    float ca = fa.x + wy1 * (fa.y - fa.x);
    float cb = fb.x + wy1 * (fb.y - fb.x);
    acc += ca + wx1 * (cb - ca);
}

// ---------------------------------------------------------------------------
// Kernel 2 (R8 shape, reordered epilogue): conv3x3 (smem tile; f32x2 over
// output-channel pairs) -> PREFETCH both center samples (coords independent
// of sigmoid) -> both pixels' sigmoids -> 8 branchy samples -> consume center.
// Block 128 = 256 px of one row (2 px/thread). grid (2, 512, 8).
// ch2 = relu(b2[2]) constant; ch1 = k3 + center.
// ---------------------------------------------------------------------------
__global__ __launch_bounds__(128) void k_seesaw(const float* __restrict__ x,
                                                const float* __restrict__ w1,
                                                const float* __restrict__ b1,
                                                const float* __restrict__ b2,
                                                float* __restrict__ out) {
    __shared__ float s_tile[3][3][264];            // [row][ch][col j], j -> w0-1+j
    __shared__ unsigned long long s_w1q[27][4];    // [tap][p] = (w1[2p][tap], w1[2p+1][tap])
    __shared__ unsigned long long s_b1q[4];
    __shared__ float  s_b2[4];

    int t = threadIdx.x;
    int w0 = blockIdx.x << 8;
    int h  = blockIdx.y;
    int b  = blockIdx.z;

    if (t < 108) {
        int p = t & 3, tap = t >> 2;
        s_w1q[tap][p] = pk2(w1[(2 * p) * 27 + tap], w1[(2 * p + 1) * 27 + tap]);
    } else if (t < 112) {
        int p = t - 108;
        s_b1q[p] = pk2(b1[2 * p], b1[2 * p + 1]);
    } else if (t < 115) {
        s_b2[t - 112] = b2[t - 112];
    }

    // ---- cooperative tile load: rows h-1..h+1, 3 channels, cols w0-1..w0+256 ----
    const float* xb = x + (size_t)b * 3 * HWSZ;
#pragma unroll
    for (int rw = 0; rw < 3; rw++) {
        int hh = h + rw - 1;
        bool vh = ((unsigned)hh < 512u);
#pragma unroll
        for (int ch = 0; ch < 3; ch++) {
            const float* src = xb + (ch << 18) + (hh << 9);
#pragma unroll
            for (int jj = 0; jj < 3; jj++) {
                int j = t + (jj << 7);
                if (j < 258) {
                    int wg = w0 - 1 + j;
                    float v = (vh && (unsigned)wg < 512u) ? __ldg(src + wg) : 0.f;
                    s_tile[rw][ch][j] = v;
                }
            }
        }
    }
    __syncthreads();

    // ---- center-sample prefetch (independent of conv/sigmoid) ----
    const uint2* f4 = g_f + (4 * NB + b) * FSZ;
    int w = w0 + (t << 1);
    float hb  = (float)h * (1.f / 511.f);
    float wb0 = (float)w * (1.f / 511.f);
    float wb1 = (float)(w + 1) * (1.f / 511.f);
    float cix  = fmaf(hb, 256.f, 255.5f);
    float ciy0 = fmaf(wb0, 256.f, 255.5f);
    float ciy1 = fmaf(wb1, 256.f, 255.5f);
    int cx = (int)cix, cy0 = (int)ciy0, cy1 = (int)ciy1;
    float cwx1  = cix - (float)cx;
    float cwy1a = ciy0 - (float)cy0;
    float cwy1b = ciy1 - (float)cy1;
    uint2 q4a = __ldg(f4 + (cx * FDIM + cy0 - FOFF));
    uint2 q4b = __ldg(f4 + (cx * FDIM + cy1 - FOFF));

    // ---- conv3x3: o-pair packed f32x2 ----
    unsigned long long zzA[4], zzB[4];
#pragma unroll
    for (int p = 0; p < 4; p++) { zzA[p] = s_b1q[p]; zzB[p] = s_b1q[p]; }

#pragma unroll
    for (int rw = 0; rw < 3; rw++) {
#pragma unroll
        for (int ch = 0; ch < 3; ch++) {
            float2 a = *reinterpret_cast<const float2*>(&s_tile[rw][ch][2 * t]);
            float2 c = *reinterpret_cast<const float2*>(&s_tile[rw][ch][2 * t + 2]);
            unsigned long long d0 = pk2(a.x, a.x);
            unsigned long long d1 = pk2(a.y, a.y);
            unsigned long long d2 = pk2(c.x, c.x);
            unsigned long long d3 = pk2(c.y, c.y);
            int tap = ch * 9 + rw * 3;
#pragma unroll
            for (int dj = 0; dj < 3; dj++) {
                ulonglong2 wa = *reinterpret_cast<const ulonglong2*>(&s_w1q[tap + dj][0]);
                ulonglong2 wb = *reinterpret_cast<const ulonglong2*>(&s_w1q[tap + dj][2]);
                unsigned long long pA = dj == 0 ? d0 : (dj == 1 ? d1 : d2);
                unsigned long long pB = dj == 0 ? d1 : (dj == 1 ? d2 : d3);
                zzA[0] = fma2(pA, wa.x, zzA[0]);
                zzA[1] = fma2(pA, wa.y, zzA[1]);
                zzA[2] = fma2(pA, wb.x, zzA[2]);
                zzA[3] = fma2(pA, wb.y, zzA[3]);
                zzB[0] = fma2(pB, wa.x, zzB[0]);
                zzB[1] = fma2(pB, wa.y, zzB[1]);
                zzB[2] = fma2(pB, wb.x, zzB[2]);
                zzB[3] = fma2(pB, wb.y, zzB[3]);
            }
        }
    }

    float z0[8], z1[8];
#pragma unroll
    for (int p = 0; p < 4; p++) {
        upk2(z0[2 * p], z0[2 * p + 1], zzA[p]);
        upk2(z1[2 * p], z1[2 * p + 1], zzB[p]);
    }

    // ---- both pixels' sigmoids back-to-back (32 independent MUFU ops) ----
    float s0[8], s1[8];
#pragma unroll
    for (int o = 0; o < 8; o++) {
        s0[o] = __fdividef(1.f, 1.f + __expf(-z0[o]));
        s1[o] = __fdividef(1.f, 1.f + __expf(-z1[o]));
    }

    // ---- 8 branchy data-dependent samples ----
    const uint2* f0 = g_f + (0 * NB + b) * FSZ;
    const uint2* f1 = g_f + (1 * NB + b) * FSZ;
    const uint2* f2 = g_f + (2 * NB + b) * FSZ;
    const uint2* f3 = g_f + (3 * NB + b) * FSZ;

    float a0p0 = 0.f, a1p0 = 0.f, a0p1 = 0.f, a1p1 = 0.f;
    samp(f0, hb + s0[0], wb0 + s0[1], a0p0);   // px0 k=0
    samp(f1, hb + s0[2], wb0 + s0[3], a0p0);   // px0 k=1
    samp(f2, hb + s0[4], wb0 + s0[5], a0p0);   // px0 k=2
    samp(f3, hb + s0[6], wb0 + s0[7], a1p0);   // px0 k=3
    samp(f0, hb + s1[0], wb1 + s1[1], a0p1);   // px1 k=0
    samp(f1, hb + s1[2], wb1 + s1[3], a0p1);   // px1 k=1
    samp(f2, hb + s1[4], wb1 + s1[5], a0p1);   // px1 k=2
    samp(f3, hb + s1[6], wb1 + s1[7], a1p1);   // px1 k=3

    // ---- consume prefetched center samples ----
    {
        float2 fa = __half22float2(*reinterpret_cast<__half2*>(&q4a.x));
        float2 fb = __half22float2(*reinterpret_cast<__half2*>(&q4a.y));
        float ca = fa.x + cwy1a * (fa.y - fa.x);
        float cb = fb.x + cwy1a * (fb.y - fb.x);
        a1p0 += ca + cwx1 * (cb - ca);
    }
    {
        float2 fa = __half22float2(*reinterpret_cast<__half2*>(&q4b.x));
        float2 fb = __half22float2(*reinterpret_cast<__half2*>(&q4b.y));
        float ca = fa.x + cwy1b * (fa.y - fa.x);
        float cb = fb.x + cwy1b * (fb.y - fb.x);
        a1p1 += ca + cwx1 * (cb - ca);
    }

    float vb2_0 = s_b2[0], vb2_1 = s_b2[1];
    float out2 = fmaxf(s_b2[2], 0.f);

    int po = b * 3 * HWSZ + (h << 9) + w;
    *reinterpret_cast<float2*>(out + po) =
        make_float2(fmaxf(a0p0 + vb2_0, 0.f), fmaxf(a0p1 + vb2_0, 0.f));
    *reinterpret_cast<float2*>(out + po + HWSZ) =
        make_float2(fmaxf(a1p0 + vb2_1, 0.f), fmaxf(a1p1 + vb2_1, 0.f));
    *reinterpret_cast<float2*>(out + po + 2 * HWSZ) = make_float2(out2, out2);
}

// ---------------------------------------------------------------------------
extern "C" void kernel_launch(void* const* d_in, const int* in_sizes, int n_in,
                              void* d_out, int out_size) {
    const float* x  = (const float*)d_in[0];
    const float* w1 = (const float*)d_in[1];
    const float* b1 = (const float*)d_in[2];
    const float* w2 = (const float*)d_in[3];
    const float* b2 = (const float*)d_in[4];
    float* out = (float*)d_out;

    k_prep<<<dim3(9, 9, NB), dim3(32, 8)>>>(x, w2);
    k_seesaw<<<dim3(2, 512, NB), 128>>>(x, w1, b1, b2, out);
}

// round 15
// speedup vs baseline: 1.1044x; 1.1044x over previous
#include <cuda_runtime.h>
#include <cuda_fp16.h>

#define HWSZ 262144           // 512*512
#define NB 8
#define FDIM 257              // live quadrant: x0,y0 in [255,511]
#define FOFF (255 * FDIM + 255)
#define FSZ (FDIM * FDIM)

// 5 scalar sample fields f_k = dot(w2_k, img), quad-packed, quadrant only.
__device__ uint2 g_f[5 * NB * FSZ];

// ---------------------------------------------------------------------------
__device__ __forceinline__ unsigned long long pk2(float lo, float hi) {
    unsigned long long r;
    asm("mov.b64 %0, {%1, %2};" : "=l"(r) : "f"(lo), "f"(hi));
    return r;
}
__device__ __forceinline__ void upk2(float& lo, float& hi, unsigned long long v) {
    asm("mov.b64 {%0, %1}, %2;" : "=f"(lo), "=f"(hi) : "l"(v));
}
__device__ __forceinline__ unsigned long long fma2(unsigned long long a,
                                                   unsigned long long b,
                                                   unsigned long long c) {
    unsigned long long d;
    asm("fma.rn.f32x2 %0, %1, %2, %3;" : "=l"(d) : "l"(a), "l"(b), "l"(c));
    return d;
}

// ---------------------------------------------------------------------------
// Kernel 1: build the quadrant fields. grid (9,9,8), block (32,8).
// ---------------------------------------------------------------------------
__global__ __launch_bounds__(256) void k_prep(const float* __restrict__ x,
                                              const float* __restrict__ w2) {
    __shared__ float4 tile[33][33];
    __shared__ float4 s_w2[5];
    int b  = blockIdx.z;
    int h0 = 255 + (blockIdx.y << 5);
    int w0 = 255 + (blockIdx.x << 5);
    int tx = threadIdx.x, ty = threadIdx.y;
    int t = (ty << 5) + tx;
    if (t < 5) s_w2[t] = make_float4(w2[3 * t], w2[3 * t + 1], w2[3 * t + 2], 0.f);

    const float* xb = x + (size_t)b * 3 * HWSZ;
#pragma unroll
    for (int r = 0; r < 5; r++) {
        int rr = ty + (r << 3);
        if (rr < 33) {
            int hh = h0 + rr;
#pragma unroll
            for (int jj = 0; jj < 2; jj++) {
                int j = tx + (jj << 5);
                if (j < 33) {
                    int ww = w0 + j;
                    float4 v = make_float4(0.f, 0.f, 0.f, 0.f);
                    if (hh < 512 && ww < 512) {
                        int hw = (hh << 9) + ww;
                        v = make_float4(xb[hw], xb[HWSZ + hw], xb[2 * HWSZ + hw], 0.f);
                    }
                    tile[rr][j] = v;
                }
            }
        }
    }
    __syncthreads();

    int fy = h0 + tx - 255;
    if (fy >= FDIM) return;
#pragma unroll
    for (int r = 0; r < 4; r++) {
        int cc = ty + (r << 3);
        int fx = w0 + cc - 255;
        if (fx >= FDIM) continue;
        float4 v00 = tile[tx][cc];
        float4 v01 = tile[tx + 1][cc];
        float4 v10 = tile[tx][cc + 1];
        float4 v11 = tile[tx + 1][cc + 1];
        int base = fx * FDIM + fy;
#pragma unroll
        for (int k = 0; k < 5; k++) {
            float4 wv = s_w2[k];
            float f00 = v00.x * wv.x + v00.y * wv.y + v00.z * wv.z;
            float f01 = v01.x * wv.x + v01.y * wv.y + v01.z * wv.z;
            float f10 = v10.x * wv.x + v10.y * wv.y + v10.z * wv.z;
            float f11 = v11.x * wv.x + v11.y * wv.y + v11.z * wv.z;
            __half2 pa = __floats2half2_rn(f00, f01);
            __half2 pb = __floats2half2_rn(f10, f11);
            uint2 q;
            q.x = *reinterpret_cast<unsigned*>(&pa);
            q.y = *reinterpret_cast<unsigned*>(&pb);
            g_f[(k * NB + b) * FSZ + base] = q;
        }
    }
}

// ---------------------------------------------------------------------------
// Bilinear sample of a quadrant field (branchy early-out, R8-proven):
// ONE scattered 8B load + 6 flops.
// ---------------------------------------------------------------------------
__device__ __forceinline__ void samp(const uint2* __restrict__ fld,
                                     float gx, float gy, float& acc) {
    float ix = fmaf(gx, 256.f, 255.5f);
    float iy = fmaf(gy, 256.f, 255.5f);
    if (ix >= 512.f || iy >= 512.f) return;
    int x0 = (int)ix, y0 = (int)iy;
    float wx1 = ix - (float)x0, wy1 = iy - (float)y0;
    uint2 q = __ldg(fld + (x0 * FDIM + y0 - FOFF));
    float2 fa = __half22float2(*reinterpret_cast<__half2*>(&q.x));
    float2 fb = __half22float2(*reinterpret_cast<__half2*>(&q.y));
    float ca = fa.x + wy1 * (fa.y - fa.x);
    float cb = fb.x + wy1 * (fb.y - fb.x);
    acc += ca + wx1 * (cb - ca);
}
// Center sample: always in-bounds, no branch.
__device__ __forceinline__ void samp_c(const uint2* __restrict__ fld,
                                       float gx, float gy, float& acc) {
    float ix = fmaf(gx, 256.f, 255.5f);
    float iy = fmaf(gy, 256.f, 255.5f);
    int x0 = (int)ix, y0 = (int)iy;
    float wx1 = ix - (float)x0, wy1 = iy - (float)y0;
    uint2 q = __ldg(fld + (x0 * FDIM + y0 - FOFF));
    float2 fa = __half22float2(*reinterpret_cast<__half2*>(&q.x));
    float2 fb = __half22float2(*reinterpret_cast<__half2*>(&q.y));
    float ca = fa.x + wy1 * (fa.y - fa.x);
    float cb = fb.x + wy1 * (fb.y - fb.x);
    acc += ca + wx1 * (cb - ca);
}

// ---------------------------------------------------------------------------
// Kernel 2 (exact R8 code; __launch_bounds__(128,16) forces 32 regs for
// full occupancy): conv3x3 (smem tile; f32x2 over output-channel pairs)
// + sigmoid + 5 field samples + epilogue.
// Block 128 = 256 px of one row (2 px/thread). grid (2, 512, 8).
// ch2 = relu(b2[2]) constant; ch1 = k3 + center.
// ---------------------------------------------------------------------------
__global__ __launch_bounds__(128, 16) void k_seesaw(const float* __restrict__ x,
                                                    const float* __restrict__ w1,
                                                    const float* __restrict__ b1,
                                                    const float* __restrict__ b2,
                                                    float* __restrict__ out) {
    __shared__ float s_tile[3][3][264];            // [row][ch][col j], j -> w0-1+j
    __shared__ unsigned long long s_w1q[27][4];    // [tap][p] = (w1[2p][tap], w1[2p+1][tap])
    __shared__ unsigned long long s_b1q[4];
    __shared__ float  s_b2[4];

    int t = threadIdx.x;
    int w0 = blockIdx.x << 8;
    int h  = blockIdx.y;
    int b  = blockIdx.z;

    if (t < 108) {
        int p = t & 3, tap = t >> 2;
        s_w1q[tap][p] = pk2(w1[(2 * p) * 27 + tap], w1[(2 * p + 1) * 27 + tap]);
    } else if (t < 112) {
        int p = t - 108;
        s_b1q[p] = pk2(b1[2 * p], b1[2 * p + 1]);
    } else if (t < 115) {
        s_b2[t - 112] = b2[t - 112];
    }

    // ---- cooperative tile load: rows h-1..h+1, 3 channels, cols w0-1..w0+256 ----
    const float* xb = x + (size_t)b * 3 * HWSZ;
#pragma unroll
    for (int rw = 0; rw < 3; rw++) {
        int hh = h + rw - 1;
        bool vh = ((unsigned)hh < 512u);
#pragma unroll
        for (int ch = 0; ch < 3; ch++) {
            const float* src = xb + (ch << 18) + (hh << 9);
#pragma unroll
            for (int jj = 0; jj < 3; jj++) {
                int j = t + (jj << 7);
                if (j < 258) {
                    int wg = w0 - 1 + j;
                    float v = (vh && (unsigned)wg < 512u) ? __ldg(src + wg) : 0.f;
                    s_tile[rw][ch][j] = v;
                }
            }
        }
    }
    __syncthreads();

    // ---- conv3x3: o-pair packed f32x2 ----
    unsigned long long zzA[4], zzB[4];
#pragma unroll
    for (int p = 0; p < 4; p++) { zzA[p] = s_b1q[p]; zzB[p] = s_b1q[p]; }

#pragma unroll
    for (int rw = 0; rw < 3; rw++) {
#pragma unroll
        for (int ch = 0; ch < 3; ch++) {
            float2 a = *reinterpret_cast<const float2*>(&s_tile[rw][ch][2 * t]);
            float2 c = *reinterpret_cast<const float2*>(&s_tile[rw][ch][2 * t + 2]);
            unsigned long long d0 = pk2(a.x, a.x);
            unsigned long long d1 = pk2(a.y, a.y);
            unsigned long long d2 = pk2(c.x, c.x);
            unsigned long long d3 = pk2(c.y, c.y);
            int tap = ch * 9 + rw * 3;
#pragma unroll
            for (int dj = 0; dj < 3; dj++) {
                ulonglong2 wa = *reinterpret_cast<const ulonglong2*>(&s_w1q[tap + dj][0]);
                ulonglong2 wb = *reinterpret_cast<const ulonglong2*>(&s_w1q[tap + dj][2]);
                unsigned long long pA = dj == 0 ? d0 : (dj == 1 ? d1 : d2);
                unsigned long long pB = dj == 0 ? d1 : (dj == 1 ? d2 : d3);
                zzA[0] = fma2(pA, wa.x, zzA[0]);
                zzA[1] = fma2(pA, wa.y, zzA[1]);
                zzA[2] = fma2(pA, wb.x, zzA[2]);
                zzA[3] = fma2(pA, wb.y, zzA[3]);
                zzB[0] = fma2(pB, wa.x, zzB[0]);
                zzB[1] = fma2(pB, wa.y, zzB[1]);
                zzB[2] = fma2(pB, wb.x, zzB[2]);
                zzB[3] = fma2(pB, wb.y, zzB[3]);
            }
        }
    }

    float z0[8], z1[8];
#pragma unroll
    for (int p = 0; p < 4; p++) {
        upk2(z0[2 * p], z0[2 * p + 1], zzA[p]);
        upk2(z1[2 * p], z1[2 * p + 1], zzB[p]);
    }

    // ---- sigmoid + 5 field samples + epilogue ----
    const uint2* f0 = g_f + (0 * NB + b) * FSZ;
    const uint2* f1 = g_f + (1 * NB + b) * FSZ;
    const uint2* f2 = g_f + (2 * NB + b) * FSZ;
    const uint2* f3 = g_f + (3 * NB + b) * FSZ;
    const uint2* f4 = g_f + (4 * NB + b) * FSZ;
    float hb = (float)h * (1.f / 511.f);
    float vb2_0 = s_b2[0], vb2_1 = s_b2[1];
    float out2 = fmaxf(s_b2[2], 0.f);
    int w = w0 + (t << 1);

    float o0[2], o1[2];
#pragma unroll
    for (int px = 0; px < 2; px++) {
        float* z = px ? z1 : z0;
        float s[8];
#pragma unroll
        for (int o = 0; o < 8; o++)
            s[o] = __fdividef(1.f, 1.f + __expf(-z[o]));
        float wb = (float)(w + px) * (1.f / 511.f);

        float a0 = 0.f, a1 = 0.f;
        samp(f0, hb + s[0], wb + s[1], a0);   // k=0
        samp(f1, hb + s[2], wb + s[3], a0);   // k=1
        samp(f2, hb + s[4], wb + s[5], a0);   // k=2
        samp(f3, hb + s[6], wb + s[7], a1);   // k=3
        samp_c(f4, hb,      wb,        a1);   // k=4 center
        o0[px] = fmaxf(a0 + vb2_0, 0.f);
        o1[px] = fmaxf(a1 + vb2_1, 0.f);
    }

    int po = b * 3 * HWSZ + (h << 9) + w;
    *reinterpret_cast<float2*>(out + po)            = make_float2(o0[0], o0[1]);
    *reinterpret_cast<float2*>(out + po + HWSZ)     = make_float2(o1[0], o1[1]);
    *reinterpret_cast<float2*>(out + po + 2 * HWSZ) = make_float2(out2, out2);
}

// ---------------------------------------------------------------------------
extern "C" void kernel_launch(void* const* d_in, const int* in_sizes, int n_in,
                              void* d_out, int out_size) {
    const float* x  = (const float*)d_in[0];
    const float* w1 = (const float*)d_in[1];
    const float* b1 = (const float*)d_in[2];
    const float* w2 = (const float*)d_in[3];
    const float* b2 = (const float*)d_in[4];
    float* out = (float*)d_out;

    k_prep<<<dim3(9, 9, NB), dim3(32, 8)>>>(x, w2);
    k_seesaw<<<dim3(2, 512, NB), 128>>>(x, w1, b1, b2, out);
}